// round 1
// baseline (speedup 1.0000x reference)
#include <cuda_runtime.h>
#include <cuda_bf16.h>

#define BINS 10

// __device__ global scratch (allocation-free rule)
__device__ double            g_loss_sum[BINS];
__device__ unsigned long long g_count[BINS];

__global__ void ghm_zero_kernel() {
    int i = threadIdx.x;
    if (i < BINS) {
        g_loss_sum[i] = 0.0;
        g_count[i]    = 0ull;
    }
}

__global__ __launch_bounds__(256, 8)
void ghm_hist_loss_kernel(const float4* __restrict__ x4,
                          const float4* __restrict__ t4,
                          const float*  __restrict__ x1,
                          const float*  __restrict__ t1,
                          int n4, int n)
{
    float ls[BINS];
    int   ct[BINS];
#pragma unroll
    for (int k = 0; k < BINS; k++) { ls[k] = 0.0f; ct[k] = 0; }

    const int stride = gridDim.x * blockDim.x;
    for (int i = blockIdx.x * blockDim.x + threadIdx.x; i < n4; i += stride) {
        float4 xv = x4[i];
        float4 tv = t4[i];
        float xs[4] = {xv.x, xv.y, xv.z, xv.w};
        float ts[4] = {tv.x, tv.y, tv.z, tv.w};
#pragma unroll
        for (int j = 0; j < 4; j++) {
            float xx = xs[j], tt = ts[j];
            float g  = fabsf(xx - tt);
            int   b  = (int)(g * 9.9999f);     // == floor(g*(BINS-1e-4)), g>=0
            b = min(b, BINS - 1);
            float loss = -(tt * __logf(xx) + (1.0f - tt) * __logf(1.0f - xx));
#pragma unroll
            for (int k = 0; k < BINS; k++) {
                if (b == k) { ls[k] += loss; ct[k] += 1; }
            }
        }
    }

    // Tail elements (n not divisible by 4) — handled by block 0 only.
    if (blockIdx.x == 0) {
        for (int i = n4 * 4 + threadIdx.x; i < n; i += blockDim.x) {
            float xx = x1[i], tt = t1[i];
            float g  = fabsf(xx - tt);
            int   b  = (int)(g * 9.9999f);
            b = min(b, BINS - 1);
            float loss = -(tt * __logf(xx) + (1.0f - tt) * __logf(1.0f - xx));
#pragma unroll
            for (int k = 0; k < BINS; k++) {
                if (b == k) { ls[k] += loss; ct[k] += 1; }
            }
        }
    }

    // Warp-level reduction of the 10 accumulators
#pragma unroll
    for (int k = 0; k < BINS; k++) {
#pragma unroll
        for (int off = 16; off > 0; off >>= 1) {
            ls[k] += __shfl_down_sync(0xffffffffu, ls[k], off);
            ct[k] += __shfl_down_sync(0xffffffffu, ct[k], off);
        }
    }

    __shared__ float        s_ls[BINS];
    __shared__ unsigned int s_ct[BINS];
    if (threadIdx.x < BINS) { s_ls[threadIdx.x] = 0.0f; s_ct[threadIdx.x] = 0u; }
    __syncthreads();

    if ((threadIdx.x & 31) == 0) {
#pragma unroll
        for (int k = 0; k < BINS; k++) {
            atomicAdd(&s_ls[k], ls[k]);
            atomicAdd(&s_ct[k], (unsigned int)ct[k]);
        }
    }
    __syncthreads();

    if (threadIdx.x < BINS) {
        atomicAdd(&g_loss_sum[threadIdx.x], (double)s_ls[threadIdx.x]);
        atomicAdd(&g_count[threadIdx.x], (unsigned long long)s_ct[threadIdx.x]);
    }
}

__global__ void ghm_finalize_kernel(float* __restrict__ out, long long N)
{
    if (threadIdx.x == 0 && blockIdx.x == 0) {
        // nonempty bins (exact integer test on exact counts)
        float nonempty = 0.0f;
#pragma unroll
        for (int k = 0; k < BINS; k++)
            nonempty += (g_count[k] > 0ull) ? 1.0f : 0.0f;

        const float Nf = (float)N;
        double total = 0.0;
#pragma unroll
        for (int k = 0; k < BINS; k++) {
            float cntf = (float)g_count[k];          // match jnp f32 cast
            float gd   = fmaxf(cntf * nonempty, 1.0f);
            float beta = Nf / gd;
            total += (double)beta * g_loss_sum[k];
        }
        out[0] = (float)(total / (double)N);
    }
}

extern "C" void kernel_launch(void* const* d_in, const int* in_sizes, int n_in,
                              void* d_out, int out_size)
{
    const float* x = (const float*)d_in[0];
    const float* t = (const float*)d_in[1];
    float* out = (float*)d_out;

    const int n  = in_sizes[0];
    const int n4 = n >> 2;

    const int threads = 256;
    int blocks = 148 * 8;                       // 8 CTAs / SM, grid-stride
    int needed = (n4 + threads - 1) / threads;
    if (needed < 1) needed = 1;
    if (blocks > needed) blocks = needed;

    ghm_zero_kernel<<<1, 32>>>();
    ghm_hist_loss_kernel<<<blocks, threads>>>(
        (const float4*)x, (const float4*)t, x, t, n4, n);
    ghm_finalize_kernel<<<1, 32>>>(out, (long long)n);
}

// round 2
// speedup vs baseline: 4.9662x; 4.9662x over previous
#include <cuda_runtime.h>
#include <cuda_bf16.h>

#define BINS 10
#define TPB  256

// __device__ global scratch (allocation-free rule)
__device__ double             g_loss_sum[BINS];
__device__ unsigned long long g_count[BINS];

__global__ void ghm_zero_kernel() {
    int i = threadIdx.x;
    if (i < BINS) {
        g_loss_sum[i] = 0.0;
        g_count[i]    = 0ull;
    }
}

__global__ __launch_bounds__(TPB, 8)
void ghm_hist_loss_kernel(const float4* __restrict__ x4,
                          const float4* __restrict__ t4,
                          const float*  __restrict__ x1,
                          const float*  __restrict__ t1,
                          int n4, int n)
{
    // acc[b*TPB + tid] : (.x = sum of log2-domain loss, .y = count) — bank-conflict-free
    __shared__ float2 acc[BINS * TPB];

    const int tid = threadIdx.x;
#pragma unroll
    for (int k = 0; k < BINS; k++)
        acc[k * TPB + tid] = make_float2(0.0f, 0.0f);
    __syncthreads();

    const int stride = gridDim.x * blockDim.x;
    for (int i = blockIdx.x * blockDim.x + tid; i < n4; i += stride) {
        float4 xv = x4[i];
        float4 tv = t4[i];
        float xs[4] = {xv.x, xv.y, xv.z, xv.w};
        float ts[4] = {tv.x, tv.y, tv.z, tv.w};
#pragma unroll
        for (int j = 0; j < 4; j++) {
            float xx = xs[j], tt = ts[j];
            float g  = fabsf(xx - tt);
            int   b  = (int)(g * 9.9999f);      // g < 1 strictly -> b in [0,9]
            // log2-domain BCE: t*l1 + (1-t)*l2 = t*(l1-l2) + l2 ; scale by -ln2 at finalize
            float l1 = __log2f(xx);
            float l2 = __log2f(1.0f - xx);
            float loss2 = fmaf(tt, l1 - l2, l2);
            int addr = b * TPB + tid;
            float2 a = acc[addr];
            a.x += loss2;
            a.y += 1.0f;
            acc[addr] = a;
        }
    }

    // tail (n not divisible by 4): block 0 only
    if (blockIdx.x == 0) {
        for (int i = n4 * 4 + tid; i < n; i += blockDim.x) {
            float xx = x1[i], tt = t1[i];
            float g  = fabsf(xx - tt);
            int   b  = (int)(g * 9.9999f);
            float l1 = __log2f(xx);
            float l2 = __log2f(1.0f - xx);
            float loss2 = fmaf(tt, l1 - l2, l2);
            int addr = b * TPB + tid;
            float2 a = acc[addr];
            a.x += loss2;
            a.y += 1.0f;
            acc[addr] = a;
        }
    }
    __syncthreads();

    // tree reduction over the tid dimension for all bins
    for (int s = TPB / 2; s > 0; s >>= 1) {
        if (tid < s) {
#pragma unroll
            for (int k = 0; k < BINS; k++) {
                float2 a = acc[k * TPB + tid];
                float2 b = acc[k * TPB + tid + s];
                a.x += b.x; a.y += b.y;
                acc[k * TPB + tid] = a;
            }
        }
        __syncthreads();
    }

    if (tid < BINS) {
        float2 a = acc[tid * TPB];
        atomicAdd(&g_loss_sum[tid], (double)a.x);
        atomicAdd(&g_count[tid], (unsigned long long)(a.y + 0.5f));
    }
}

__global__ void ghm_finalize_kernel(float* __restrict__ out, long long N)
{
    if (threadIdx.x == 0 && blockIdx.x == 0) {
        const double NEG_LN2 = -0.6931471805599453;  // loss = -ln2 * (log2-domain sum)
        float nonempty = 0.0f;
#pragma unroll
        for (int k = 0; k < BINS; k++)
            nonempty += (g_count[k] > 0ull) ? 1.0f : 0.0f;

        const float Nf = (float)N;
        double total = 0.0;
#pragma unroll
        for (int k = 0; k < BINS; k++) {
            float cntf = (float)g_count[k];          // match jnp f32 cast
            float gd   = fmaxf(cntf * nonempty, 1.0f);
            float beta = Nf / gd;
            total += (double)beta * (NEG_LN2 * g_loss_sum[k]);
        }
        out[0] = (float)(total / (double)N);
    }
}

extern "C" void kernel_launch(void* const* d_in, const int* in_sizes, int n_in,
                              void* d_out, int out_size)
{
    const float* x = (const float*)d_in[0];
    const float* t = (const float*)d_in[1];
    float* out = (float*)d_out;

    const int n  = in_sizes[0];
    const int n4 = n >> 2;

    const int threads = TPB;
    int blocks = 148 * 8;                       // 8 CTAs / SM, grid-stride
    int needed = (n4 + threads - 1) / threads;
    if (needed < 1) needed = 1;
    if (blocks > needed) blocks = needed;

    ghm_zero_kernel<<<1, 32>>>();
    ghm_hist_loss_kernel<<<blocks, threads>>>(
        (const float4*)x, (const float4*)t, x, t, n4, n);
    ghm_finalize_kernel<<<1, 32>>>(out, (long long)n);
}